// round 1
// baseline (speedup 1.0000x reference)
#include <cuda_runtime.h>
#include <cuda_bf16.h>
#include <cstdio>

// Problem constants
#define BATCH 2
#define SEQ   2048
#define HID   2048
#define NH    32
#define NG    8
#define HD    64
#define KVD   (NG*HD)   // 512
#define MTOT  (BATCH*SEQ) // 4096

// Scratch (device globals; no allocation allowed)
__device__ float g_q[(size_t)BATCH*NH*SEQ*HD];   // [b,h,s,d]
__device__ float g_k[(size_t)BATCH*NG*SEQ*HD];   // [b,g,s,d]
__device__ float g_v[(size_t)BATCH*NG*SEQ*HD];
__device__ float g_o[(size_t)MTOT*HID];          // [b,s, h*d]  (attention output)

// ---------------------------------------------------------------------------
// SGEMM: C = A[M,K] @ W[K,N] + bias[N]
// 128x128 tile, BK=8, 256 threads, 8x8 per-thread microtile.
// MODE 0: plain row-major store
// MODE 1: scatter to q layout  [b, h=n/64, s, d=n%64]   (NH=32)
// MODE 2: scatter to kv layout [b, g=n/64, s, d=n%64]   (NG=8)
// ---------------------------------------------------------------------------
template<int MODE>
__global__ __launch_bounds__(256) void sgemm_kernel(
    const float* __restrict__ A, const float* __restrict__ W,
    const float* __restrict__ bias, float* __restrict__ C,
    int M, int N, int K)
{
    __shared__ float As[8][128];   // A transposed: As[k][m]
    __shared__ float Bs[8][128];   // Bs[k][n]

    const int tid = threadIdx.x;
    const int tx = tid & 15;       // 16 thread-cols
    const int ty = tid >> 4;       // 16 thread-rows
    const int row0 = blockIdx.y * 128;
    const int col0 = blockIdx.x * 128;

    const int aRow = tid >> 1;          // 0..127
    const int aCol = (tid & 1) * 4;     // 0 or 4
    const int bRow = tid >> 5;          // 0..7
    const int bCol = (tid & 31) * 4;    // 0..124

    const float* Ap = A + (size_t)(row0 + aRow) * K + aCol;
    const float* Wp = W + (size_t)bRow * N + col0 + bCol;

    float acc[8][8];
    #pragma unroll
    for (int i = 0; i < 8; i++)
        #pragma unroll
        for (int j = 0; j < 8; j++) acc[i][j] = 0.0f;

    for (int kt = 0; kt < K; kt += 8) {
        float4 a4 = *(const float4*)Ap;
        float4 b4 = *(const float4*)Wp;
        As[aCol + 0][aRow] = a4.x;
        As[aCol + 1][aRow] = a4.y;
        As[aCol + 2][aRow] = a4.z;
        As[aCol + 3][aRow] = a4.w;
        *(float4*)&Bs[bRow][bCol] = b4;
        __syncthreads();

        #pragma unroll
        for (int kk = 0; kk < 8; kk++) {
            float af[8], bf[8];
            *(float4*)&af[0] = *(const float4*)&As[kk][ty * 8];
            *(float4*)&af[4] = *(const float4*)&As[kk][ty * 8 + 4];
            *(float4*)&bf[0] = *(const float4*)&Bs[kk][tx * 8];
            *(float4*)&bf[4] = *(const float4*)&Bs[kk][tx * 8 + 4];
            #pragma unroll
            for (int i = 0; i < 8; i++)
                #pragma unroll
                for (int j = 0; j < 8; j++)
                    acc[i][j] = fmaf(af[i], bf[j], acc[i][j]);
        }
        __syncthreads();
        Ap += 8;
        Wp += (size_t)8 * N;
    }

    #pragma unroll
    for (int i = 0; i < 8; i++) {
        const int m = row0 + ty * 8 + i;
        const int b = m >> 11;         // SEQ = 2048
        const int s = m & 2047;
        #pragma unroll
        for (int j = 0; j < 8; j++) {
            const int n = col0 + tx * 8 + j;
            const float val = acc[i][j] + bias[n];
            if (MODE == 0) {
                C[(size_t)m * N + n] = val;
            } else if (MODE == 1) {
                const int h = n >> 6, d = n & 63;
                C[(((size_t)(b * NH + h)) * SEQ + s) * HD + d] = val;
            } else {
                const int g = n >> 6, d = n & 63;
                C[(((size_t)(b * NG + g)) * SEQ + s) * HD + d] = val;
            }
        }
    }
}

// ---------------------------------------------------------------------------
// Flash attention (fp32). One block = one (b, h, 64-query tile).
// 256 threads as a 16x16 grid; thread (ty,tx) owns 4 q-rows x 4 cols.
// K/V tiles of 64 keys; online softmax; P staged via smem for the PV GEMM.
// Dynamic smem: Qt[64][68] + Kt[64][68] + Ps[64][68] + Vs[64][64] = 68608 B
// ---------------------------------------------------------------------------
#define QT_PITCH 68
#define ATTN_SMEM_BYTES (3 * 64 * QT_PITCH * 4 + 64 * 64 * 4)

__global__ __launch_bounds__(256) void attn_kernel(
    const float* __restrict__ q, const float* __restrict__ k,
    const float* __restrict__ v, float* __restrict__ o)
{
    extern __shared__ float sm[];
    float* Qt = sm;                         // [d][q]  pitch 68
    float* Kt = sm + 64 * QT_PITCH;         // [d][kv] pitch 68
    float* Ps = sm + 2 * 64 * QT_PITCH;     // [q][kv] pitch 68
    float* Vs = sm + 3 * 64 * QT_PITCH;     // [kv][d] pitch 64

    const int tid = threadIdx.x;
    const int tx = tid & 15;
    const int ty = tid >> 4;
    const int qt = blockIdx.x;
    const int h  = blockIdx.y;
    const int b  = blockIdx.z;
    const int g  = h >> 2;  // REP = 4
    const float scale = 0.125f; // 1/sqrt(64)

    const float* qbase = q + (((size_t)(b * NH + h)) * SEQ + qt * 64) * HD;
    const float* kbase = k + ((size_t)(b * NG + g)) * SEQ * HD;
    const float* vbase = v + ((size_t)(b * NG + g)) * SEQ * HD;

    // Load Q tile transposed: Qt[d][s]
    #pragma unroll
    for (int t = 0; t < 16; t++) {
        const int idx = tid + t * 256;       // 0..4095
        const int s = idx >> 6, d = idx & 63;
        Qt[d * QT_PITCH + s] = qbase[idx];
    }

    float m_i[4], l_i[4], oacc[4][4];
    #pragma unroll
    for (int i = 0; i < 4; i++) {
        m_i[i] = -1e30f; l_i[i] = 0.0f;
        #pragma unroll
        for (int j = 0; j < 4; j++) oacc[i][j] = 0.0f;
    }

    for (int kt = 0; kt < SEQ / 64; kt++) {
        __syncthreads();  // previous PV done (and Q load visible on first iter)

        const float* kp = kbase + (size_t)kt * 64 * HD;
        const float* vp = vbase + (size_t)kt * 64 * HD;
        #pragma unroll
        for (int t = 0; t < 16; t++) {
            const int idx = tid + t * 256;
            const int s = idx >> 6, d = idx & 63;
            Kt[d * QT_PITCH + s] = kp[idx];
            Vs[s * 64 + d]       = vp[idx];
        }
        __syncthreads();

        // S tile: sv[i][j] = sum_d Q[q0+i][d] * K[k0+j][d]
        float sv[4][4];
        #pragma unroll
        for (int i = 0; i < 4; i++)
            #pragma unroll
            for (int j = 0; j < 4; j++) sv[i][j] = 0.0f;

        #pragma unroll
        for (int kk = 0; kk < 64; kk++) {
            const float4 qf = *(const float4*)&Qt[kk * QT_PITCH + ty * 4];
            const float4 kf = *(const float4*)&Kt[kk * QT_PITCH + tx * 4];
            const float qa[4] = {qf.x, qf.y, qf.z, qf.w};
            const float ka[4] = {kf.x, kf.y, kf.z, kf.w};
            #pragma unroll
            for (int i = 0; i < 4; i++)
                #pragma unroll
                for (int j = 0; j < 4; j++)
                    sv[i][j] = fmaf(qa[i], ka[j], sv[i][j]);
        }

        // Online softmax per q-row (reduce across the 16 tx threads = half-warp)
        #pragma unroll
        for (int i = 0; i < 4; i++) {
            #pragma unroll
            for (int j = 0; j < 4; j++) sv[i][j] *= scale;

            float mx = fmaxf(fmaxf(sv[i][0], sv[i][1]), fmaxf(sv[i][2], sv[i][3]));
            #pragma unroll
            for (int off = 8; off >= 1; off >>= 1)
                mx = fmaxf(mx, __shfl_xor_sync(0xffffffffu, mx, off));

            const float m_new = fmaxf(m_i[i], mx);
            const float corr  = __expf(m_i[i] - m_new);
            float p[4], rs = 0.0f;
            #pragma unroll
            for (int j = 0; j < 4; j++) { p[j] = __expf(sv[i][j] - m_new); rs += p[j]; }
            #pragma unroll
            for (int off = 8; off >= 1; off >>= 1)
                rs += __shfl_xor_sync(0xffffffffu, rs, off);

            l_i[i] = l_i[i] * corr + rs;
            m_i[i] = m_new;
            #pragma unroll
            for (int j = 0; j < 4; j++) oacc[i][j] *= corr;
            #pragma unroll
            for (int j = 0; j < 4; j++)
                Ps[(ty * 4 + i) * QT_PITCH + tx * 4 + j] = p[j];
        }
        __syncthreads();

        // O += P @ V   (thread owns d-cols tx*4..tx*4+3)
        #pragma unroll
        for (int kk = 0; kk < 64; kk++) {
            const float4 vf = *(const float4*)&Vs[kk * 64 + tx * 4];
            #pragma unroll
            for (int i = 0; i < 4; i++) {
                const float pv = Ps[(ty * 4 + i) * QT_PITCH + kk];
                oacc[i][0] = fmaf(pv, vf.x, oacc[i][0]);
                oacc[i][1] = fmaf(pv, vf.y, oacc[i][1]);
                oacc[i][2] = fmaf(pv, vf.z, oacc[i][2]);
                oacc[i][3] = fmaf(pv, vf.w, oacc[i][3]);
            }
        }
    }

    // Write normalized output to [b, s, h*64 + d]
    #pragma unroll
    for (int i = 0; i < 4; i++) {
        const float inv = 1.0f / l_i[i];
        const int s = qt * 64 + ty * 4 + i;
        float* op = o + ((size_t)b * SEQ + s) * HID + h * HD + tx * 4;
        op[0] = oacc[i][0] * inv;
        op[1] = oacc[i][1] * inv;
        op[2] = oacc[i][2] * inv;
        op[3] = oacc[i][3] * inv;
    }
}

// ---------------------------------------------------------------------------
extern "C" void kernel_launch(void* const* d_in, const int* in_sizes, int n_in,
                              void* d_out, int out_size)
{
    const float* X  = (const float*)d_in[0];
    const float* Wq = (const float*)d_in[1];
    const float* bq = (const float*)d_in[2];
    const float* Wk = (const float*)d_in[3];
    const float* bk = (const float*)d_in[4];
    const float* Wv = (const float*)d_in[5];
    const float* bv = (const float*)d_in[6];
    const float* Wo = (const float*)d_in[7];
    const float* bo = (const float*)d_in[8];
    float* out = (float*)d_out;

    float *qp, *kp, *vp, *op;
    cudaGetSymbolAddress((void**)&qp, g_q);
    cudaGetSymbolAddress((void**)&kp, g_k);
    cudaGetSymbolAddress((void**)&vp, g_v);
    cudaGetSymbolAddress((void**)&op, g_o);

    cudaFuncSetAttribute(attn_kernel,
                         cudaFuncAttributeMaxDynamicSharedMemorySize,
                         ATTN_SMEM_BYTES);

    dim3 blk(256);

    // Q projection: [4096,2048] @ [2048,2048]
    sgemm_kernel<1><<<dim3(HID / 128, MTOT / 128), blk>>>(X, Wq, bq, qp, MTOT, HID, HID);
    // K/V projections: [4096,2048] @ [2048,512]
    sgemm_kernel<2><<<dim3(KVD / 128, MTOT / 128), blk>>>(X, Wk, bk, kp, MTOT, KVD, HID);
    sgemm_kernel<2><<<dim3(KVD / 128, MTOT / 128), blk>>>(X, Wv, bv, vp, MTOT, KVD, HID);

    // Attention: grid = (q-tiles, heads, batch)
    attn_kernel<<<dim3(SEQ / 64, NH, BATCH), blk, ATTN_SMEM_BYTES>>>(qp, kp, vp, op);

    // Output projection: [4096,2048] @ [2048,2048] -> d_out
    sgemm_kernel<0><<<dim3(HID / 128, MTOT / 128), blk>>>(op, Wo, bo, out, MTOT, HID, HID);
}

// round 2
// speedup vs baseline: 1.6285x; 1.6285x over previous
#include <cuda_runtime.h>
#include <cuda_bf16.h>
#include <cstdint>

// Problem constants
#define BATCH 2
#define SEQ   2048
#define HID   2048
#define NH    32
#define NG    8
#define HD    64
#define KVD   (NG*HD)     // 512
#define MTOT  (BATCH*SEQ) // 4096

// Scratch (device globals; no allocation allowed)
__device__ float g_q[(size_t)BATCH*NH*SEQ*HD];   // [b,h,s,d]
__device__ float g_k[(size_t)BATCH*NG*SEQ*HD];   // [b,g,s,d]
__device__ float g_v[(size_t)BATCH*NG*SEQ*HD];
__device__ float g_o[(size_t)MTOT*HID];          // [b,s,h*d]

// ---------------------------------------------------------------------------
// tf32 helpers. HW mma.tf32 reads only the top 19 bits of each 32-bit operand,
// so feeding raw fp32 acts as truncation-to-tf32. lo = x - trunc(x) is exact.
// 3xTF32: x*y ~= lo_x*x + x*lo_y + x*y  (each operand implicitly truncated).
// ---------------------------------------------------------------------------
__device__ __forceinline__ float tf32_trunc(float x) {
    return __uint_as_float(__float_as_uint(x) & 0xffffe000u);
}
__device__ __forceinline__ float tf32_lo(float x) { return x - tf32_trunc(x); }

__device__ __forceinline__ void mma_tf32(float d[4],
    uint32_t a0, uint32_t a1, uint32_t a2, uint32_t a3,
    uint32_t b0, uint32_t b1)
{
    asm volatile(
        "mma.sync.aligned.m16n8k8.row.col.f32.tf32.tf32.f32 "
        "{%0,%1,%2,%3}, {%4,%5,%6,%7}, {%8,%9}, {%0,%1,%2,%3};\n"
        : "+f"(d[0]), "+f"(d[1]), "+f"(d[2]), "+f"(d[3])
        : "r"(a0), "r"(a1), "r"(a2), "r"(a3), "r"(b0), "r"(b1));
}

// ---------------------------------------------------------------------------
// 3xTF32 GEMM: C = A[M,K] @ W[K,N] + bias[N]
// Block 128x128, BK=32, 256 threads (8 warps in 4x2), warp tile 32x64.
// MODE 0: row-major store; MODE 1: scatter to [b,h,s,d]; MODE 2: [b,g,s,d].
// smem: As[128][36] + As_lo + Bs[32][132] + Bs_lo = 70656 B (dynamic)
// ---------------------------------------------------------------------------
#define GEMM_SMEM_BYTES ((128*36*2 + 32*132*2) * 4)

template<int MODE>
__global__ __launch_bounds__(256) void gemm_tf32_kernel(
    const float* __restrict__ A, const float* __restrict__ W,
    const float* __restrict__ bias, float* __restrict__ C,
    int M, int N, int K)
{
    extern __shared__ float sm[];
    float* As = sm;                 // [128][36]
    float* Al = As + 128 * 36;
    float* Bs = Al + 128 * 36;      // [32][132]
    float* Bl = Bs + 32 * 132;

    const int tid  = threadIdx.x;
    const int lane = tid & 31;
    const int wid  = tid >> 5;
    const int g = lane >> 2;        // 0..7
    const int c = lane & 3;         // 0..3
    const int wm0 = (wid & 3) * 32; // warp row base within tile
    const int wn0 = (wid >> 2) * 64;
    const int row0 = blockIdx.y * 128;
    const int col0 = blockIdx.x * 128;

    float acc[2][8][4];
    #pragma unroll
    for (int mt = 0; mt < 2; mt++)
        #pragma unroll
        for (int nt = 0; nt < 8; nt++)
            #pragma unroll
            for (int j = 0; j < 4; j++) acc[mt][nt][j] = 0.0f;

    for (int k0 = 0; k0 < K; k0 += 32) {
        __syncthreads();
        // A tile: 128 rows x 32 cols
        #pragma unroll
        for (int i = 0; i < 4; i++) {
            const int idx = tid + i * 256;        // 0..1023 float4s
            const int r = idx >> 3, c4 = (idx & 7) * 4;
            float4 a4 = *(const float4*)(A + (size_t)(row0 + r) * K + k0 + c4);
            float4 l4;
            l4.x = tf32_lo(a4.x); l4.y = tf32_lo(a4.y);
            l4.z = tf32_lo(a4.z); l4.w = tf32_lo(a4.w);
            *(float4*)(As + r * 36 + c4) = a4;
            *(float4*)(Al + r * 36 + c4) = l4;
        }
        // B tile: 32 rows x 128 cols
        #pragma unroll
        for (int i = 0; i < 4; i++) {
            const int idx = tid + i * 256;
            const int r = idx >> 5, c4 = (idx & 31) * 4;
            float4 b4 = *(const float4*)(W + (size_t)(k0 + r) * N + col0 + c4);
            float4 l4;
            l4.x = tf32_lo(b4.x); l4.y = tf32_lo(b4.y);
            l4.z = tf32_lo(b4.z); l4.w = tf32_lo(b4.w);
            *(float4*)(Bs + r * 132 + c4) = b4;
            *(float4*)(Bl + r * 132 + c4) = l4;
        }
        __syncthreads();

        #pragma unroll
        for (int kk = 0; kk < 4; kk++) {
            uint32_t ah[2][4], al[2][4];
            #pragma unroll
            for (int mt = 0; mt < 2; mt++) {
                const int rb = (wm0 + mt * 16 + g) * 36 + kk * 8 + c;
                const int rb8 = rb + 8 * 36;
                ah[mt][0] = __float_as_uint(As[rb]);
                ah[mt][1] = __float_as_uint(As[rb8]);
                ah[mt][2] = __float_as_uint(As[rb + 4]);
                ah[mt][3] = __float_as_uint(As[rb8 + 4]);
                al[mt][0] = __float_as_uint(Al[rb]);
                al[mt][1] = __float_as_uint(Al[rb8]);
                al[mt][2] = __float_as_uint(Al[rb + 4]);
                al[mt][3] = __float_as_uint(Al[rb8 + 4]);
            }
            #pragma unroll
            for (int nt = 0; nt < 8; nt++) {
                const int nb = (kk * 8 + c) * 132 + wn0 + nt * 8 + g;
                const uint32_t bh0 = __float_as_uint(Bs[nb]);
                const uint32_t bh1 = __float_as_uint(Bs[nb + 4 * 132]);
                const uint32_t bl0 = __float_as_uint(Bl[nb]);
                const uint32_t bl1 = __float_as_uint(Bl[nb + 4 * 132]);
                #pragma unroll
                for (int mt = 0; mt < 2; mt++) {
                    mma_tf32(acc[mt][nt], al[mt][0], al[mt][1], al[mt][2], al[mt][3], bh0, bh1);
                    mma_tf32(acc[mt][nt], ah[mt][0], ah[mt][1], ah[mt][2], ah[mt][3], bl0, bl1);
                    mma_tf32(acc[mt][nt], ah[mt][0], ah[mt][1], ah[mt][2], ah[mt][3], bh0, bh1);
                }
            }
        }
    }

    // Epilogue: bias add + scatter
    #pragma unroll
    for (int mt = 0; mt < 2; mt++) {
        const int r = row0 + wm0 + mt * 16 + g;   // and r+8
        #pragma unroll
        for (int nt = 0; nt < 8; nt++) {
            const int n = col0 + wn0 + nt * 8 + 2 * c;
            const float bv0 = bias[n], bv1 = bias[n + 1];
            float v0 = acc[mt][nt][0] + bv0;
            float v1 = acc[mt][nt][1] + bv1;
            float v2 = acc[mt][nt][2] + bv0;
            float v3 = acc[mt][nt][3] + bv1;
            if (MODE == 0) {
                *(float2*)(C + (size_t)r * N + n)       = make_float2(v0, v1);
                *(float2*)(C + (size_t)(r + 8) * N + n) = make_float2(v2, v3);
            } else {
                const int hh = n >> 6, d = n & 63;
                const int HN = (MODE == 1) ? NH : NG;
                const int b0 = r >> 11, s0 = r & 2047;
                const int b1 = (r + 8) >> 11, s1 = (r + 8) & 2047;
                *(float2*)(C + (((size_t)(b0 * HN + hh)) * SEQ + s0) * HD + d) = make_float2(v0, v1);
                *(float2*)(C + (((size_t)(b1 * HN + hh)) * SEQ + s1) * HD + d) = make_float2(v2, v3);
            }
        }
    }
}

// ---------------------------------------------------------------------------
// Flash attention with 3xTF32 mma. Block = (b, h, 64-query tile), 128 threads
// (4 warps, each owns a 16-row m-tile). K/V tiles of 64 keys via smem; Q frags
// held in registers; P staged through smem for the PV mma.
// smem: Ks[64][68] + Vs[64][68] + Ps[64][68] = 52224 B (dynamic)
// ---------------------------------------------------------------------------
#define ATTN_SMEM_BYTES (3 * 64 * 68 * 4)

__global__ __launch_bounds__(128) void attn_mma_kernel(
    const float* __restrict__ q, const float* __restrict__ k,
    const float* __restrict__ v, float* __restrict__ o)
{
    extern __shared__ float sm[];
    float* Ks = sm;             // [64][68]  (key, d)
    float* Vs = Ks + 64 * 68;   // [64][68]  (key, d)
    float* Ps = Vs + 64 * 68;   // [64][68]  (q, key)

    const int tid  = threadIdx.x;
    const int lane = tid & 31;
    const int wid  = tid >> 5;       // 0..3
    const int g = lane >> 2, c = lane & 3;
    const int wr0 = wid * 16;        // warp's q-row base within 64-tile

    const int qt = blockIdx.x;
    const int h  = blockIdx.y;
    const int b  = blockIdx.z;
    const int gh = h >> 2;           // REP = 4

    const float* qb = q + (((size_t)(b * NH + h)) * SEQ + qt * 64 + wr0) * HD;
    const float* kb = k + ((size_t)(b * NG + gh)) * SEQ * HD;
    const float* vb = v + ((size_t)(b * NG + gh)) * SEQ * HD;

    // Q fragments in registers (hi = raw fp32, lo = split)
    uint32_t qh[8][4], ql[8][4];
    #pragma unroll
    for (int kt = 0; kt < 8; kt++) {
        const float x0 = qb[g * 64 + kt * 8 + c];
        const float x1 = qb[(g + 8) * 64 + kt * 8 + c];
        const float x2 = qb[g * 64 + kt * 8 + c + 4];
        const float x3 = qb[(g + 8) * 64 + kt * 8 + c + 4];
        qh[kt][0] = __float_as_uint(x0); ql[kt][0] = __float_as_uint(tf32_lo(x0));
        qh[kt][1] = __float_as_uint(x1); ql[kt][1] = __float_as_uint(tf32_lo(x1));
        qh[kt][2] = __float_as_uint(x2); ql[kt][2] = __float_as_uint(tf32_lo(x2));
        qh[kt][3] = __float_as_uint(x3); ql[kt][3] = __float_as_uint(tf32_lo(x3));
    }

    float m0 = -1e30f, m1 = -1e30f, l0 = 0.0f, l1 = 0.0f;
    float oacc[8][4];
    #pragma unroll
    for (int nt = 0; nt < 8; nt++)
        #pragma unroll
        for (int j = 0; j < 4; j++) oacc[nt][j] = 0.0f;

    for (int t = 0; t < SEQ / 64; t++) {
        __syncthreads();    // protect Ks/Vs from previous iteration's readers
        const float* kp = kb + (size_t)t * 64 * HD;
        const float* vp = vb + (size_t)t * 64 * HD;
        #pragma unroll
        for (int i = 0; i < 8; i++) {
            const int idx = tid + i * 128;        // 0..1023 float4s
            const int r = idx >> 4, c4 = (idx & 15) * 4;
            *(float4*)(Ks + r * 68 + c4) = *(const float4*)(kp + r * 64 + c4);
            *(float4*)(Vs + r * 68 + c4) = *(const float4*)(vp + r * 64 + c4);
        }
        __syncthreads();

        // S = Q @ K^T  (3xTF32)
        float sv[8][4];
        #pragma unroll
        for (int nt = 0; nt < 8; nt++)
            #pragma unroll
            for (int j = 0; j < 4; j++) sv[nt][j] = 0.0f;

        #pragma unroll
        for (int kt = 0; kt < 8; kt++) {
            #pragma unroll
            for (int nt = 0; nt < 8; nt++) {
                const int nb = (nt * 8 + g) * 68 + kt * 8 + c;
                const float f0 = Ks[nb], f1 = Ks[nb + 4];
                const uint32_t bh0 = __float_as_uint(f0);
                const uint32_t bh1 = __float_as_uint(f1);
                const uint32_t bl0 = __float_as_uint(tf32_lo(f0));
                const uint32_t bl1 = __float_as_uint(tf32_lo(f1));
                mma_tf32(sv[nt], ql[kt][0], ql[kt][1], ql[kt][2], ql[kt][3], bh0, bh1);
                mma_tf32(sv[nt], qh[kt][0], qh[kt][1], qh[kt][2], qh[kt][3], bl0, bl1);
                mma_tf32(sv[nt], qh[kt][0], qh[kt][1], qh[kt][2], qh[kt][3], bh0, bh1);
            }
        }

        // Online softmax. Thread owns rows (wr0+g) [sv[.][0..1]] and (wr0+g+8).
        float mx0 = -1e30f, mx1 = -1e30f;
        #pragma unroll
        for (int nt = 0; nt < 8; nt++) {
            sv[nt][0] *= 0.125f; sv[nt][1] *= 0.125f;
            sv[nt][2] *= 0.125f; sv[nt][3] *= 0.125f;
            mx0 = fmaxf(mx0, fmaxf(sv[nt][0], sv[nt][1]));
            mx1 = fmaxf(mx1, fmaxf(sv[nt][2], sv[nt][3]));
        }
        mx0 = fmaxf(mx0, __shfl_xor_sync(0xffffffffu, mx0, 1));
        mx0 = fmaxf(mx0, __shfl_xor_sync(0xffffffffu, mx0, 2));
        mx1 = fmaxf(mx1, __shfl_xor_sync(0xffffffffu, mx1, 1));
        mx1 = fmaxf(mx1, __shfl_xor_sync(0xffffffffu, mx1, 2));

        const float nm0 = fmaxf(m0, mx0), nm1 = fmaxf(m1, mx1);
        const float corr0 = __expf(m0 - nm0), corr1 = __expf(m1 - nm1);
        float ls0 = 0.0f, ls1 = 0.0f;
        #pragma unroll
        for (int nt = 0; nt < 8; nt++) {
            const float p0 = __expf(sv[nt][0] - nm0);
            const float p1 = __expf(sv[nt][1] - nm0);
            const float p2 = __expf(sv[nt][2] - nm1);
            const float p3 = __expf(sv[nt][3] - nm1);
            ls0 += p0 + p1; ls1 += p2 + p3;
            *(float2*)(Ps + (wr0 + g) * 68 + nt * 8 + 2 * c)     = make_float2(p0, p1);
            *(float2*)(Ps + (wr0 + g + 8) * 68 + nt * 8 + 2 * c) = make_float2(p2, p3);
        }
        ls0 += __shfl_xor_sync(0xffffffffu, ls0, 1);
        ls0 += __shfl_xor_sync(0xffffffffu, ls0, 2);
        ls1 += __shfl_xor_sync(0xffffffffu, ls1, 1);
        ls1 += __shfl_xor_sync(0xffffffffu, ls1, 2);
        l0 = l0 * corr0 + ls0; m0 = nm0;
        l1 = l1 * corr1 + ls1; m1 = nm1;
        #pragma unroll
        for (int nt = 0; nt < 8; nt++) {
            oacc[nt][0] *= corr0; oacc[nt][1] *= corr0;
            oacc[nt][2] *= corr1; oacc[nt][3] *= corr1;
        }
        __syncwarp();

        // O += P @ V  (3xTF32). A = P (k = key), B = V (n = d).
        #pragma unroll
        for (int kt = 0; kt < 8; kt++) {
            const int pb = (wr0 + g) * 68 + kt * 8 + c;
            const float p0 = Ps[pb], p1 = Ps[pb + 8 * 68];
            const float p2 = Ps[pb + 4], p3 = Ps[pb + 8 * 68 + 4];
            const uint32_t ph0 = __float_as_uint(p0), ph1 = __float_as_uint(p1);
            const uint32_t ph2 = __float_as_uint(p2), ph3 = __float_as_uint(p3);
            const uint32_t pl0 = __float_as_uint(tf32_lo(p0));
            const uint32_t pl1 = __float_as_uint(tf32_lo(p1));
            const uint32_t pl2 = __float_as_uint(tf32_lo(p2));
            const uint32_t pl3 = __float_as_uint(tf32_lo(p3));
            #pragma unroll
            for (int nt = 0; nt < 8; nt++) {
                const int vbi = (kt * 8 + c) * 68 + nt * 8 + g;
                const float f0 = Vs[vbi], f1 = Vs[vbi + 4 * 68];
                const uint32_t vh0 = __float_as_uint(f0);
                const uint32_t vh1 = __float_as_uint(f1);
                const uint32_t vl0 = __float_as_uint(tf32_lo(f0));
                const uint32_t vl1 = __float_as_uint(tf32_lo(f1));
                mma_tf32(oacc[nt], pl0, pl1, pl2, pl3, vh0, vh1);
                mma_tf32(oacc[nt], ph0, ph1, ph2, ph3, vl0, vl1);
                mma_tf32(oacc[nt], ph0, ph1, ph2, ph3, vh0, vh1);
            }
        }
    }

    // Epilogue: normalize and store to [b, s, h*64 + d]
    const float inv0 = 1.0f / l0, inv1 = 1.0f / l1;
    float* ob = o + ((size_t)b * SEQ + qt * 64 + wr0) * HID + h * HD;
    #pragma unroll
    for (int nt = 0; nt < 8; nt++) {
        const int d = nt * 8 + 2 * c;
        *(float2*)(ob + (size_t)g * HID + d) =
            make_float2(oacc[nt][0] * inv0, oacc[nt][1] * inv0);
        *(float2*)(ob + (size_t)(g + 8) * HID + d) =
            make_float2(oacc[nt][2] * inv1, oacc[nt][3] * inv1);
    }
}

// ---------------------------------------------------------------------------
extern "C" void kernel_launch(void* const* d_in, const int* in_sizes, int n_in,
                              void* d_out, int out_size)
{
    const float* X  = (const float*)d_in[0];
    const float* Wq = (const float*)d_in[1];
    const float* bq = (const float*)d_in[2];
    const float* Wk = (const float*)d_in[3];
    const float* bk = (const float*)d_in[4];
    const float* Wv = (const float*)d_in[5];
    const float* bv = (const float*)d_in[6];
    const float* Wo = (const float*)d_in[7];
    const float* bo = (const float*)d_in[8];
    float* out = (float*)d_out;

    float *qp, *kp, *vp, *op;
    cudaGetSymbolAddress((void**)&qp, g_q);
    cudaGetSymbolAddress((void**)&kp, g_k);
    cudaGetSymbolAddress((void**)&vp, g_v);
    cudaGetSymbolAddress((void**)&op, g_o);

    cudaFuncSetAttribute(gemm_tf32_kernel<0>, cudaFuncAttributeMaxDynamicSharedMemorySize, GEMM_SMEM_BYTES);
    cudaFuncSetAttribute(gemm_tf32_kernel<1>, cudaFuncAttributeMaxDynamicSharedMemorySize, GEMM_SMEM_BYTES);
    cudaFuncSetAttribute(gemm_tf32_kernel<2>, cudaFuncAttributeMaxDynamicSharedMemorySize, GEMM_SMEM_BYTES);
    cudaFuncSetAttribute(attn_mma_kernel, cudaFuncAttributeMaxDynamicSharedMemorySize, ATTN_SMEM_BYTES);

    dim3 blk(256);
    // Q projection
    gemm_tf32_kernel<1><<<dim3(HID / 128, MTOT / 128), blk, GEMM_SMEM_BYTES>>>(X, Wq, bq, qp, MTOT, HID, HID);
    // K/V projections
    gemm_tf32_kernel<2><<<dim3(KVD / 128, MTOT / 128), blk, GEMM_SMEM_BYTES>>>(X, Wk, bk, kp, MTOT, KVD, HID);
    gemm_tf32_kernel<2><<<dim3(KVD / 128, MTOT / 128), blk, GEMM_SMEM_BYTES>>>(X, Wv, bv, vp, MTOT, KVD, HID);
    // Attention
    attn_mma_kernel<<<dim3(SEQ / 64, NH, BATCH), dim3(128), ATTN_SMEM_BYTES>>>(qp, kp, vp, op);
    // Output projection
    gemm_tf32_kernel<0><<<dim3(HID / 128, MTOT / 128), blk, GEMM_SMEM_BYTES>>>(op, Wo, bo, out, MTOT, HID, HID);
}

// round 3
// speedup vs baseline: 1.7457x; 1.0720x over previous
#include <cuda_runtime.h>
#include <cuda_bf16.h>
#include <cstdint>

// Problem constants
#define BATCH 2
#define SEQ   2048
#define HID   2048
#define NH    32
#define NG    8
#define HD    64
#define KVD   (NG*HD)     // 512
#define MTOT  (BATCH*SEQ) // 4096

// Scratch (device globals; no allocation allowed)
__device__ float g_q[(size_t)BATCH*NH*SEQ*HD];   // [b,h,s,d]
__device__ float g_k[(size_t)BATCH*NG*SEQ*HD];   // [b,g,s,d]
__device__ float g_v[(size_t)BATCH*NG*SEQ*HD];
__device__ float g_o[(size_t)MTOT*HID];          // [b,s,h*d]

// ---------------------------------------------------------------------------
// bf16 split helpers. x = hi + lo with hi = bf16(x), lo = bf16(x - hi).
// x*y ~= lo_x*hi_y + hi_x*lo_y + hi_x*hi_y  (dropped lo*lo term ~2^-18 rel).
// Pack two K-adjacent values into one .b32 (low half = lower k).
// ---------------------------------------------------------------------------
__device__ __forceinline__ void split2(float x0, float x1, uint32_t& h, uint32_t& l) {
    __nv_bfloat162 hb = __floats2bfloat162_rn(x0, x1);
    const float r0 = x0 - __bfloat162float(hb.x);
    const float r1 = x1 - __bfloat162float(hb.y);
    __nv_bfloat162 lb = __floats2bfloat162_rn(r0, r1);
    h = *reinterpret_cast<uint32_t*>(&hb);
    l = *reinterpret_cast<uint32_t*>(&lb);
}

__device__ __forceinline__ void mma_bf16(float d[4], const uint32_t a[4],
                                         uint32_t b0, uint32_t b1) {
    asm volatile(
        "mma.sync.aligned.m16n8k16.row.col.f32.bf16.bf16.f32 "
        "{%0,%1,%2,%3}, {%4,%5,%6,%7}, {%8,%9}, {%0,%1,%2,%3};\n"
        : "+f"(d[0]), "+f"(d[1]), "+f"(d[2]), "+f"(d[3])
        : "r"(a[0]), "r"(a[1]), "r"(a[2]), "r"(a[3]), "r"(b0), "r"(b1));
}

// ---------------------------------------------------------------------------
// 3x-bf16 GEMM: C = A[M,K] @ W[K,N] + bias[N]
// Block 128x128, BK=32, 256 threads (8 warps 4x2), warp tile 32x64.
// Double-buffered smem + register prefetch. Tiles stored as packed bf16x2
// K-pairs: A/B hi+lo, each [128][PITCH] uint32 (16 k-pairs + pad).
// MODE 0: row-major store; MODE 1: scatter [b,h,s,d]; MODE 2: [b,g,s,d].
// ---------------------------------------------------------------------------
#define GP 18                     // uint32 pitch (16 k-pairs + 2 pad)
#define GBUF (128 * GP)           // uint32 per matrix per stage
#define GEMM_SMEM_BYTES (2 * 4 * GBUF * 4)   // 2 stages x {Ah,Al,Bh,Bl} = 73728

template<int MODE>
__global__ __launch_bounds__(256) void gemm_bf16_kernel(
    const float* __restrict__ A, const float* __restrict__ W,
    const float* __restrict__ bias, float* __restrict__ C,
    int M, int N, int K)
{
    extern __shared__ uint32_t smu[];

    const int tid  = threadIdx.x;
    const int lane = tid & 31;
    const int wid  = tid >> 5;
    const int g = lane >> 2;        // 0..7
    const int c = lane & 3;         // 0..3
    const int wm0 = (wid & 3) * 32;
    const int wn0 = (wid >> 2) * 64;
    const int row0 = blockIdx.y * 128;
    const int col0 = blockIdx.x * 128;

    // per-thread loader coords
    const int aR  = tid >> 3;            // A row (two rows per... 256 thr / 8 f4-per-row)
    const int aQ  = tid & 7;             // which float4 within the 32-k row
    // B units: u = tid + i*256 ; n = u & 127 ; kg = u >> 7

    float acc[2][8][4];
    #pragma unroll
    for (int mt = 0; mt < 2; mt++)
        #pragma unroll
        for (int nt = 0; nt < 8; nt++)
            #pragma unroll
            for (int j = 0; j < 4; j++) acc[mt][nt][j] = 0.0f;

    const int NT = K / 32;

    // ---- load tile 0 into stage 0 ----
    {
        uint32_t* Ah = smu;
        uint32_t* Al = Ah + GBUF;
        uint32_t* Bh = Al + GBUF;
        uint32_t* Bl = Bh + GBUF;
        #pragma unroll
        for (int i = 0; i < 4; i++) {
            const int idx = tid + i * 256;
            const int r = idx >> 3, q = idx & 7;
            float4 a4 = *(const float4*)(A + (size_t)(row0 + r) * K + q * 4);
            uint32_t h0, l0, h1, l1;
            split2(a4.x, a4.y, h0, l0);
            split2(a4.z, a4.w, h1, l1);
            Ah[r * GP + q * 2] = h0; Ah[r * GP + q * 2 + 1] = h1;
            Al[r * GP + q * 2] = l0; Al[r * GP + q * 2 + 1] = l1;
        }
        #pragma unroll
        for (int i = 0; i < 4; i++) {
            const int u = tid + i * 256;
            const int n = u & 127, kg = u >> 7;
            float w0 = W[(size_t)(kg * 4 + 0) * N + col0 + n];
            float w1 = W[(size_t)(kg * 4 + 1) * N + col0 + n];
            float w2 = W[(size_t)(kg * 4 + 2) * N + col0 + n];
            float w3 = W[(size_t)(kg * 4 + 3) * N + col0 + n];
            uint32_t h0, l0, h1, l1;
            split2(w0, w1, h0, l0);
            split2(w2, w3, h1, l1);
            Bh[n * GP + kg * 2] = h0; Bh[n * GP + kg * 2 + 1] = h1;
            Bl[n * GP + kg * 2] = l0; Bl[n * GP + kg * 2 + 1] = l1;
        }
    }

    for (int kt = 0; kt < NT; kt++) {
        __syncthreads();
        const uint32_t* Ah = smu + (kt & 1) * 4 * GBUF;
        const uint32_t* Al = Ah + GBUF;
        const uint32_t* Bh = Al + GBUF;
        const uint32_t* Bl = Bh + GBUF;

        // prefetch next tile into registers
        float4 pa[4];
        float  pb[4][4];
        if (kt + 1 < NT) {
            const int k0 = (kt + 1) * 32;
            #pragma unroll
            for (int i = 0; i < 4; i++) {
                const int idx = tid + i * 256;
                const int r = idx >> 3, q = idx & 7;
                pa[i] = *(const float4*)(A + (size_t)(row0 + r) * K + k0 + q * 4);
            }
            #pragma unroll
            for (int i = 0; i < 4; i++) {
                const int u = tid + i * 256;
                const int n = u & 127, kg = u >> 7;
                #pragma unroll
                for (int j = 0; j < 4; j++)
                    pb[i][j] = W[(size_t)(k0 + kg * 4 + j) * N + col0 + n];
            }
        }

        // compute: 2 k16-chunks
        #pragma unroll
        for (int kk = 0; kk < 2; kk++) {
            uint32_t ah[2][4], al[2][4];
            #pragma unroll
            for (int mt = 0; mt < 2; mt++) {
                const int rb = (wm0 + mt * 16 + g) * GP + kk * 8 + c;
                const int rb8 = rb + 8 * GP;
                ah[mt][0] = Ah[rb];     ah[mt][1] = Ah[rb8];
                ah[mt][2] = Ah[rb + 4]; ah[mt][3] = Ah[rb8 + 4];
                al[mt][0] = Al[rb];     al[mt][1] = Al[rb8];
                al[mt][2] = Al[rb + 4]; al[mt][3] = Al[rb8 + 4];
            }
            #pragma unroll
            for (int nt = 0; nt < 8; nt++) {
                const int nb = (wn0 + nt * 8 + g) * GP + kk * 8 + c;
                const uint32_t bh0 = Bh[nb], bh1 = Bh[nb + 4];
                const uint32_t bl0 = Bl[nb], bl1 = Bl[nb + 4];
                #pragma unroll
                for (int mt = 0; mt < 2; mt++) {
                    mma_bf16(acc[mt][nt], al[mt], bh0, bh1);
                    mma_bf16(acc[mt][nt], ah[mt], bl0, bl1);
                    mma_bf16(acc[mt][nt], ah[mt], bh0, bh1);
                }
            }
        }

        // store prefetched tile into the other stage (safe: other stage unused now)
        if (kt + 1 < NT) {
            uint32_t* nAh = smu + ((kt + 1) & 1) * 4 * GBUF;
            uint32_t* nAl = nAh + GBUF;
            uint32_t* nBh = nAl + GBUF;
            uint32_t* nBl = nBh + GBUF;
            #pragma unroll
            for (int i = 0; i < 4; i++) {
                const int idx = tid + i * 256;
                const int r = idx >> 3, q = idx & 7;
                uint32_t h0, l0, h1, l1;
                split2(pa[i].x, pa[i].y, h0, l0);
                split2(pa[i].z, pa[i].w, h1, l1);
                nAh[r * GP + q * 2] = h0; nAh[r * GP + q * 2 + 1] = h1;
                nAl[r * GP + q * 2] = l0; nAl[r * GP + q * 2 + 1] = l1;
            }
            #pragma unroll
            for (int i = 0; i < 4; i++) {
                const int u = tid + i * 256;
                const int n = u & 127, kg = u >> 7;
                uint32_t h0, l0, h1, l1;
                split2(pb[i][0], pb[i][1], h0, l0);
                split2(pb[i][2], pb[i][3], h1, l1);
                nBh[n * GP + kg * 2] = h0; nBh[n * GP + kg * 2 + 1] = h1;
                nBl[n * GP + kg * 2] = l0; nBl[n * GP + kg * 2 + 1] = l1;
            }
        }
    }

    // Epilogue: bias add + scatter
    #pragma unroll
    for (int mt = 0; mt < 2; mt++) {
        const int r = row0 + wm0 + mt * 16 + g;   // and r+8
        #pragma unroll
        for (int nt = 0; nt < 8; nt++) {
            const int n = col0 + wn0 + nt * 8 + 2 * c;
            const float bv0 = bias[n], bv1 = bias[n + 1];
            float v0 = acc[mt][nt][0] + bv0;
            float v1 = acc[mt][nt][1] + bv1;
            float v2 = acc[mt][nt][2] + bv0;
            float v3 = acc[mt][nt][3] + bv1;
            if (MODE == 0) {
                *(float2*)(C + (size_t)r * N + n)       = make_float2(v0, v1);
                *(float2*)(C + (size_t)(r + 8) * N + n) = make_float2(v2, v3);
            } else {
                const int hh = n >> 6, d = n & 63;
                const int HN = (MODE == 1) ? NH : NG;
                const int b0 = r >> 11, s0 = r & 2047;
                const int b1 = (r + 8) >> 11, s1 = (r + 8) & 2047;
                *(float2*)(C + (((size_t)(b0 * HN + hh)) * SEQ + s0) * HD + d) = make_float2(v0, v1);
                *(float2*)(C + (((size_t)(b1 * HN + hh)) * SEQ + s1) * HD + d) = make_float2(v2, v3);
            }
        }
    }
}

// ---------------------------------------------------------------------------
// Flash attention, 3x-bf16 mma. Block = (b, h, 64-query tile), 128 threads
// (4 warps, each owns 16 q-rows). 64-key tiles; online softmax; P packed to
// bf16 hi/lo pairs in smem for the PV mma.
// smem (uint32): Kh/Kl[64][33] (key, d-pair), Vh/Vl[64][33] (d, key-pair),
//                Ph/Pl[64][33] (q, key-pair)  -> 50688 B
// ---------------------------------------------------------------------------
#define AP 33
#define ABUF (64 * AP)
#define ATTN_SMEM_BYTES (6 * ABUF * 4)

__global__ __launch_bounds__(128) void attn_mma_kernel(
    const float* __restrict__ q, const float* __restrict__ k,
    const float* __restrict__ v, float* __restrict__ o)
{
    extern __shared__ uint32_t smu[];
    uint32_t* Kh = smu;
    uint32_t* Kl = Kh + ABUF;
    uint32_t* Vh = Kl + ABUF;
    uint32_t* Vl = Vh + ABUF;
    uint32_t* Ph = Vl + ABUF;
    uint32_t* Pl = Ph + ABUF;

    const int tid  = threadIdx.x;
    const int lane = tid & 31;
    const int wid  = tid >> 5;
    const int g = lane >> 2, c = lane & 3;
    const int wr0 = wid * 16;

    const int qt = blockIdx.x;
    const int h  = blockIdx.y;
    const int b  = blockIdx.z;
    const int gh = h >> 2;           // REP = 4

    const float* qb = q + (((size_t)(b * NH + h)) * SEQ + qt * 64 + wr0) * HD;
    const float* kb = k + ((size_t)(b * NG + gh)) * SEQ * HD;
    const float* vb = v + ((size_t)(b * NG + gh)) * SEQ * HD;

    // Q fragments: 4 k16-chunks over d=64
    uint32_t qh[4][4], ql[4][4];
    #pragma unroll
    for (int kt = 0; kt < 4; kt++) {
        float2 x0 = *(const float2*)(qb + (size_t)g * 64 + kt * 16 + 2 * c);
        float2 x1 = *(const float2*)(qb + (size_t)(g + 8) * 64 + kt * 16 + 2 * c);
        float2 x2 = *(const float2*)(qb + (size_t)g * 64 + kt * 16 + 2 * c + 8);
        float2 x3 = *(const float2*)(qb + (size_t)(g + 8) * 64 + kt * 16 + 2 * c + 8);
        split2(x0.x, x0.y, qh[kt][0], ql[kt][0]);
        split2(x1.x, x1.y, qh[kt][1], ql[kt][1]);
        split2(x2.x, x2.y, qh[kt][2], ql[kt][2]);
        split2(x3.x, x3.y, qh[kt][3], ql[kt][3]);
    }

    float m0 = -1e30f, m1 = -1e30f, l0 = 0.0f, l1 = 0.0f;
    float oacc[8][4];
    #pragma unroll
    for (int nt = 0; nt < 8; nt++)
        #pragma unroll
        for (int j = 0; j < 4; j++) oacc[nt][j] = 0.0f;

    for (int t = 0; t < SEQ / 64; t++) {
        __syncthreads();    // previous iteration's readers of K/V done
        const float* kp = kb + (size_t)t * 64 * HD;
        const float* vp = vb + (size_t)t * 64 * HD;

        // K: [key][d] -> Kh/Kl[key][d-pair]
        #pragma unroll
        for (int i = 0; i < 8; i++) {
            const int idx = tid + i * 128;       // 0..1023 float4s
            const int r = idx >> 4, q4 = idx & 15;
            float4 kv = *(const float4*)(kp + (size_t)r * 64 + q4 * 4);
            uint32_t h0, lo0, h1, lo1;
            split2(kv.x, kv.y, h0, lo0);
            split2(kv.z, kv.w, h1, lo1);
            Kh[r * AP + q4 * 2] = h0; Kh[r * AP + q4 * 2 + 1] = h1;
            Kl[r * AP + q4 * 2] = lo0; Kl[r * AP + q4 * 2 + 1] = lo1;
        }
        // V: [key][d] -> Vh/Vl[d][key-pair] (pack adjacent keys)
        #pragma unroll
        for (int i = 0; i < 8; i++) {
            const int u = tid + i * 128;         // 0..1023
            const int d2 = (u & 31) * 2, kpi = u >> 5;
            float2 va = *(const float2*)(vp + (size_t)(2 * kpi) * 64 + d2);
            float2 vbx = *(const float2*)(vp + (size_t)(2 * kpi + 1) * 64 + d2);
            uint32_t h0, lo0, h1, lo1;
            split2(va.x, vbx.x, h0, lo0);
            split2(va.y, vbx.y, h1, lo1);
            Vh[d2 * AP + kpi] = h0; Vh[(d2 + 1) * AP + kpi] = h1;
            Vl[d2 * AP + kpi] = lo0; Vl[(d2 + 1) * AP + kpi] = lo1;
        }
        __syncthreads();

        // S = Q @ K^T (3x-bf16)
        float sv[8][4];
        #pragma unroll
        for (int nt = 0; nt < 8; nt++)
            #pragma unroll
            for (int j = 0; j < 4; j++) sv[nt][j] = 0.0f;

        #pragma unroll
        for (int kt = 0; kt < 4; kt++) {
            #pragma unroll
            for (int nt = 0; nt < 8; nt++) {
                const int nb = (nt * 8 + g) * AP + kt * 8 + c;
                const uint32_t bh0 = Kh[nb], bh1 = Kh[nb + 4];
                const uint32_t bl0 = Kl[nb], bl1 = Kl[nb + 4];
                mma_bf16(sv[nt], ql[kt], bh0, bh1);
                mma_bf16(sv[nt], qh[kt], bl0, bl1);
                mma_bf16(sv[nt], qh[kt], bh0, bh1);
            }
        }

        // Online softmax: thread owns rows (wr0+g) [sv[.][0..1]], (wr0+g+8).
        float mx0 = -1e30f, mx1 = -1e30f;
        #pragma unroll
        for (int nt = 0; nt < 8; nt++) {
            sv[nt][0] *= 0.125f; sv[nt][1] *= 0.125f;
            sv[nt][2] *= 0.125f; sv[nt][3] *= 0.125f;
            mx0 = fmaxf(mx0, fmaxf(sv[nt][0], sv[nt][1]));
            mx1 = fmaxf(mx1, fmaxf(sv[nt][2], sv[nt][3]));
        }
        mx0 = fmaxf(mx0, __shfl_xor_sync(0xffffffffu, mx0, 1));
        mx0 = fmaxf(mx0, __shfl_xor_sync(0xffffffffu, mx0, 2));
        mx1 = fmaxf(mx1, __shfl_xor_sync(0xffffffffu, mx1, 1));
        mx1 = fmaxf(mx1, __shfl_xor_sync(0xffffffffu, mx1, 2));

        const float nm0 = fmaxf(m0, mx0), nm1 = fmaxf(m1, mx1);
        const float corr0 = __expf(m0 - nm0), corr1 = __expf(m1 - nm1);
        float ls0 = 0.0f, ls1 = 0.0f;
        #pragma unroll
        for (int nt = 0; nt < 8; nt++) {
            const float p0 = __expf(sv[nt][0] - nm0);
            const float p1 = __expf(sv[nt][1] - nm0);
            const float p2 = __expf(sv[nt][2] - nm1);
            const float p3 = __expf(sv[nt][3] - nm1);
            ls0 += p0 + p1; ls1 += p2 + p3;
            uint32_t hh, ll;
            split2(p0, p1, hh, ll);
            Ph[(wr0 + g) * AP + nt * 4 + c] = hh;
            Pl[(wr0 + g) * AP + nt * 4 + c] = ll;
            split2(p2, p3, hh, ll);
            Ph[(wr0 + g + 8) * AP + nt * 4 + c] = hh;
            Pl[(wr0 + g + 8) * AP + nt * 4 + c] = ll;
        }
        ls0 += __shfl_xor_sync(0xffffffffu, ls0, 1);
        ls0 += __shfl_xor_sync(0xffffffffu, ls0, 2);
        ls1 += __shfl_xor_sync(0xffffffffu, ls1, 1);
        ls1 += __shfl_xor_sync(0xffffffffu, ls1, 2);
        l0 = l0 * corr0 + ls0; m0 = nm0;
        l1 = l1 * corr1 + ls1; m1 = nm1;
        #pragma unroll
        for (int nt = 0; nt < 8; nt++) {
            oacc[nt][0] *= corr0; oacc[nt][1] *= corr0;
            oacc[nt][2] *= corr1; oacc[nt][3] *= corr1;
        }
        __syncwarp();

        // O += P @ V  (3x-bf16); k = key (4 chunks), n = d (8 tiles)
        #pragma unroll
        for (int kt = 0; kt < 4; kt++) {
            uint32_t ph[4], pl[4];
            const int pb0 = (wr0 + g) * AP + kt * 8 + c;
            const int pb8 = pb0 + 8 * AP;
            ph[0] = Ph[pb0]; ph[1] = Ph[pb8]; ph[2] = Ph[pb0 + 4]; ph[3] = Ph[pb8 + 4];
            pl[0] = Pl[pb0]; pl[1] = Pl[pb8]; pl[2] = Pl[pb0 + 4]; pl[3] = Pl[pb8 + 4];
            #pragma unroll
            for (int nt = 0; nt < 8; nt++) {
                const int vbi = (nt * 8 + g) * AP + kt * 8 + c;
                const uint32_t vh0 = Vh[vbi], vh1 = Vh[vbi + 4];
                const uint32_t vl0 = Vl[vbi], vl1 = Vl[vbi + 4];
                mma_bf16(oacc[nt], pl, vh0, vh1);
                mma_bf16(oacc[nt], ph, vl0, vl1);
                mma_bf16(oacc[nt], ph, vh0, vh1);
            }
        }
    }

    // Epilogue: normalize and store to [b, s, h*64 + d]
    const float inv0 = 1.0f / l0, inv1 = 1.0f / l1;
    float* ob = o + ((size_t)b * SEQ + qt * 64 + wr0) * HID + h * HD;
    #pragma unroll
    for (int nt = 0; nt < 8; nt++) {
        const int d = nt * 8 + 2 * c;
        *(float2*)(ob + (size_t)g * HID + d) =
            make_float2(oacc[nt][0] * inv0, oacc[nt][1] * inv0);
        *(float2*)(ob + (size_t)(g + 8) * HID + d) =
            make_float2(oacc[nt][2] * inv1, oacc[nt][3] * inv1);
    }
}

// ---------------------------------------------------------------------------
extern "C" void kernel_launch(void* const* d_in, const int* in_sizes, int n_in,
                              void* d_out, int out_size)
{
    const float* X  = (const float*)d_in[0];
    const float* Wq = (const float*)d_in[1];
    const float* bq = (const float*)d_in[2];
    const float* Wk = (const float*)d_in[3];
    const float* bk = (const float*)d_in[4];
    const float* Wv = (const float*)d_in[5];
    const float* bv = (const float*)d_in[6];
    const float* Wo = (const float*)d_in[7];
    const float* bo = (const float*)d_in[8];
    float* out = (float*)d_out;

    float *qp, *kp, *vp, *op;
    cudaGetSymbolAddress((void**)&qp, g_q);
    cudaGetSymbolAddress((void**)&kp, g_k);
    cudaGetSymbolAddress((void**)&vp, g_v);
    cudaGetSymbolAddress((void**)&op, g_o);

    cudaFuncSetAttribute(gemm_bf16_kernel<0>, cudaFuncAttributeMaxDynamicSharedMemorySize, GEMM_SMEM_BYTES);
    cudaFuncSetAttribute(gemm_bf16_kernel<1>, cudaFuncAttributeMaxDynamicSharedMemorySize, GEMM_SMEM_BYTES);
    cudaFuncSetAttribute(gemm_bf16_kernel<2>, cudaFuncAttributeMaxDynamicSharedMemorySize, GEMM_SMEM_BYTES);
    cudaFuncSetAttribute(attn_mma_kernel, cudaFuncAttributeMaxDynamicSharedMemorySize, ATTN_SMEM_BYTES);

    dim3 blk(256);
    // Q projection
    gemm_bf16_kernel<1><<<dim3(HID / 128, MTOT / 128), blk, GEMM_SMEM_BYTES>>>(X, Wq, bq, qp, MTOT, HID, HID);
    // K/V projections
    gemm_bf16_kernel<2><<<dim3(KVD / 128, MTOT / 128), blk, GEMM_SMEM_BYTES>>>(X, Wk, bk, kp, MTOT, KVD, HID);
    gemm_bf16_kernel<2><<<dim3(KVD / 128, MTOT / 128), blk, GEMM_SMEM_BYTES>>>(X, Wv, bv, vp, MTOT, KVD, HID);
    // Attention
    attn_mma_kernel<<<dim3(SEQ / 64, NH, BATCH), dim3(128), ATTN_SMEM_BYTES>>>(qp, kp, vp, op);
    // Output projection
    gemm_bf16_kernel<0><<<dim3(HID / 128, MTOT / 128), blk, GEMM_SMEM_BYTES>>>(op, Wo, bo, out, MTOT, HID, HID);
}

// round 4
// speedup vs baseline: 3.1577x; 1.8089x over previous
#include <cuda_runtime.h>
#include <cuda_bf16.h>
#include <cstdint>

#define BATCH 2
#define SEQ   2048
#define HID   2048
#define NH    32
#define NG    8
#define HD    64
#define KVD   (NG*HD)     // 512
#define MTOT  (BATCH*SEQ) // 4096

typedef __nv_bfloat16 bf16;

// ---------------- device scratch (no allocation allowed) ----------------
__device__ bf16 g_xh[(size_t)MTOT*HID],  g_xl[(size_t)MTOT*HID];
__device__ bf16 g_wqh[(size_t)HID*HID],  g_wql[(size_t)HID*HID];
__device__ bf16 g_wkh[(size_t)HID*KVD],  g_wkl[(size_t)HID*KVD];
__device__ bf16 g_wvh[(size_t)HID*KVD],  g_wvl[(size_t)HID*KVD];
__device__ bf16 g_woh[(size_t)HID*HID],  g_wol[(size_t)HID*HID];
__device__ bf16 g_qh[(size_t)BATCH*NH*SEQ*HD], g_ql[(size_t)BATCH*NH*SEQ*HD];
__device__ bf16 g_kh[(size_t)BATCH*NG*SEQ*HD], g_kl[(size_t)BATCH*NG*SEQ*HD];
__device__ bf16 g_vh[(size_t)BATCH*NG*HD*SEQ], g_vl[(size_t)BATCH*NG*HD*SEQ]; // [b,g,d,s]
__device__ bf16 g_oh[(size_t)MTOT*HID],  g_ol[(size_t)MTOT*HID];

// ---------------- helpers ----------------
__device__ __forceinline__ void split2(float x0, float x1, uint32_t& h, uint32_t& l) {
    __nv_bfloat162 hb = __floats2bfloat162_rn(x0, x1);
    const float r0 = x0 - __bfloat162float(hb.x);
    const float r1 = x1 - __bfloat162float(hb.y);
    __nv_bfloat162 lb = __floats2bfloat162_rn(r0, r1);
    h = *reinterpret_cast<uint32_t*>(&hb);
    l = *reinterpret_cast<uint32_t*>(&lb);
}

__device__ __forceinline__ void mma_bf16(float d[4], const uint32_t a[4],
                                         uint32_t b0, uint32_t b1) {
    asm volatile(
        "mma.sync.aligned.m16n8k16.row.col.f32.bf16.bf16.f32 "
        "{%0,%1,%2,%3}, {%4,%5,%6,%7}, {%8,%9}, {%0,%1,%2,%3};\n"
        : "+f"(d[0]), "+f"(d[1]), "+f"(d[2]), "+f"(d[3])
        : "r"(a[0]), "r"(a[1]), "r"(a[2]), "r"(a[3]), "r"(b0), "r"(b1));
}

__device__ __forceinline__ void ldsm4(uint32_t& r0, uint32_t& r1, uint32_t& r2,
                                      uint32_t& r3, uint32_t addr) {
    asm volatile("ldmatrix.sync.aligned.m8n8.x4.shared.b16 {%0,%1,%2,%3}, [%4];"
                 : "=r"(r0), "=r"(r1), "=r"(r2), "=r"(r3) : "r"(addr));
}
__device__ __forceinline__ void ldsm4t(uint32_t& r0, uint32_t& r1, uint32_t& r2,
                                       uint32_t& r3, uint32_t addr) {
    asm volatile("ldmatrix.sync.aligned.m8n8.x4.trans.shared.b16 {%0,%1,%2,%3}, [%4];"
                 : "=r"(r0), "=r"(r1), "=r"(r2), "=r"(r3) : "r"(addr));
}

__device__ __forceinline__ void cp16(uint32_t saddr, const void* gaddr) {
    asm volatile("cp.async.cg.shared.global [%0], [%1], 16;"
                 :: "r"(saddr), "l"(gaddr) : "memory");
}
#define CP_COMMIT() asm volatile("cp.async.commit_group;" ::: "memory")
#define CP_WAIT0()  asm volatile("cp.async.wait_group 0;"  ::: "memory")

// ---------------- fp32 -> bf16 hi/lo convert ----------------
__global__ __launch_bounds__(256) void convert_kernel(
    const float* __restrict__ src, bf16* __restrict__ h, bf16* __restrict__ l, int n4)
{
    const int i = blockIdx.x * blockDim.x + threadIdx.x;
    if (i >= n4) return;
    float4 v = reinterpret_cast<const float4*>(src)[i];
    uint32_t h0, l0, h1, l1;
    split2(v.x, v.y, h0, l0);
    split2(v.z, v.w, h1, l1);
    reinterpret_cast<uint32_t*>(h)[i * 2]     = h0;
    reinterpret_cast<uint32_t*>(h)[i * 2 + 1] = h1;
    reinterpret_cast<uint32_t*>(l)[i * 2]     = l0;
    reinterpret_cast<uint32_t*>(l)[i * 2 + 1] = l1;
}

// ---------------------------------------------------------------------------
// 3x-bf16 GEMM, A/B pre-split bf16 in gmem. Block 128x128, BK=32, 256 thr
// (8 warps 4x2, warp tile 32x64). cp.async double buffering + ldmatrix frags.
// MODE 0: fp32 row-major (+bias)        -> Cf
// MODE 1: bf16 hi/lo scatter [b,h,s,d]  -> Ch/Cl
// MODE 2: bf16 hi/lo scatter [b,g,s,d], scaled by 0.125 (softmax scale)
// MODE 3: bf16 hi/lo transposed scatter [b,g,d,s]
// ---------------------------------------------------------------------------
#define GAP 40    // A smem pitch (bf16): 32 k + 8 pad (80B rows, conflict-free)
#define GBP 136   // B smem pitch (bf16): 128 n + 8 pad (272B rows)
#define GA_BYTES (128 * GAP * 2)          // 10240
#define GB_BYTES (32 * GBP * 2)           // 8704
#define GSTAGE   (2 * GA_BYTES + 2 * GB_BYTES)  // 37888
#define GEMM_SMEM (2 * GSTAGE)                  // 75776

template<int MODE>
__global__ __launch_bounds__(256, 2) void gemm_kernel(
    const bf16* __restrict__ Ah, const bf16* __restrict__ Al,
    const bf16* __restrict__ Bh, const bf16* __restrict__ Bl,
    const float* __restrict__ bias,
    float* __restrict__ Cf, bf16* __restrict__ Ch, bf16* __restrict__ Cl,
    int M, int N, int K)
{
    extern __shared__ char smc[];
    const uint32_t sbase = (uint32_t)__cvta_generic_to_shared(smc);

    const int tid  = threadIdx.x;
    const int lane = tid & 31;
    const int wid  = tid >> 5;
    const int g = lane >> 2, c = lane & 3;
    const int quad = lane >> 3, r8 = lane & 7;
    const int wm0 = (wid & 3) * 32;
    const int wn0 = (wid >> 2) * 64;
    const int row0 = blockIdx.y * 128;
    const int col0 = blockIdx.x * 128;

    float acc[2][8][4];
    #pragma unroll
    for (int mt = 0; mt < 2; mt++)
        #pragma unroll
        for (int nt = 0; nt < 8; nt++)
            #pragma unroll
            for (int j = 0; j < 4; j++) acc[mt][nt][j] = 0.0f;

    const int NT = K / 32;

    // ---- tile fill via cp.async ----
    auto fill = [&](int kt, int st) {
        const int k0 = kt * 32;
        const uint32_t s0 = sbase + st * GSTAGE;
        #pragma unroll
        for (int i = 0; i < 2; i++) {
            const int idx = tid + i * 256;            // 0..511
            const int r = idx >> 2, q = (idx & 3) * 8;
            const size_t go = (size_t)(row0 + r) * K + k0 + q;
            cp16(s0 + (r * GAP + q) * 2,            Ah + go);
            cp16(s0 + GA_BYTES + (r * GAP + q) * 2, Al + go);
        }
        #pragma unroll
        for (int i = 0; i < 2; i++) {
            const int idx = tid + i * 256;
            const int r = idx >> 4, q = (idx & 15) * 8;
            const size_t go = (size_t)(k0 + r) * N + col0 + q;
            cp16(s0 + 2 * GA_BYTES + (r * GBP + q) * 2,            Bh + go);
            cp16(s0 + 2 * GA_BYTES + GB_BYTES + (r * GBP + q) * 2, Bl + go);
        }
    };

    fill(0, 0); CP_COMMIT();

    const int arow = (quad & 1) * 8 + r8;   // A/B lane row offset
    const int acol = (quad >> 1) * 8;       // A/B lane col offset

    for (int kt = 0; kt < NT; kt++) {
        CP_WAIT0();
        __syncthreads();
        if (kt + 1 < NT) { fill(kt + 1, (kt + 1) & 1); CP_COMMIT(); }
        const uint32_t s0 = sbase + (kt & 1) * GSTAGE;

        #pragma unroll
        for (int kk = 0; kk < 2; kk++) {
            uint32_t ah[2][4], al[2][4];
            #pragma unroll
            for (int mt = 0; mt < 2; mt++) {
                const uint32_t aaddr =
                    s0 + ((wm0 + mt * 16 + arow) * GAP + kk * 16 + acol) * 2;
                ldsm4(ah[mt][0], ah[mt][1], ah[mt][2], ah[mt][3], aaddr);
                ldsm4(al[mt][0], al[mt][1], al[mt][2], al[mt][3], aaddr + GA_BYTES);
            }
            #pragma unroll
            for (int np = 0; np < 4; np++) {
                const uint32_t baddr = s0 + 2 * GA_BYTES +
                    ((kk * 16 + arow) * GBP + wn0 + np * 16 + acol) * 2;
                uint32_t bh0, bh1, bh2, bh3, bl0, bl1, bl2, bl3;
                ldsm4t(bh0, bh1, bh2, bh3, baddr);
                ldsm4t(bl0, bl1, bl2, bl3, baddr + GB_BYTES);
                #pragma unroll
                for (int mt = 0; mt < 2; mt++) {
                    mma_bf16(acc[mt][2*np],   al[mt], bh0, bh1);
                    mma_bf16(acc[mt][2*np],   ah[mt], bl0, bl1);
                    mma_bf16(acc[mt][2*np],   ah[mt], bh0, bh1);
                    mma_bf16(acc[mt][2*np+1], al[mt], bh2, bh3);
                    mma_bf16(acc[mt][2*np+1], ah[mt], bl2, bl3);
                    mma_bf16(acc[mt][2*np+1], ah[mt], bh2, bh3);
                }
            }
        }
    }

    // ---- epilogue ----
    #pragma unroll
    for (int mt = 0; mt < 2; mt++) {
        const int r = row0 + wm0 + mt * 16 + g;     // and r+8
        #pragma unroll
        for (int nt = 0; nt < 8; nt++) {
            const int n = col0 + wn0 + nt * 8 + 2 * c;
            const float bv0 = bias[n], bv1 = bias[n + 1];
            float v0 = acc[mt][nt][0] + bv0;
            float v1 = acc[mt][nt][1] + bv1;
            float v2 = acc[mt][nt][2] + bv0;
            float v3 = acc[mt][nt][3] + bv1;
            if (MODE == 0) {
                *(float2*)(Cf + (size_t)r * N + n)       = make_float2(v0, v1);
                *(float2*)(Cf + (size_t)(r + 8) * N + n) = make_float2(v2, v3);
            } else if (MODE == 1 || MODE == 2) {
                if (MODE == 2) { v0 *= 0.125f; v1 *= 0.125f; v2 *= 0.125f; v3 *= 0.125f; }
                const int HN = (MODE == 1) ? NH : NG;
                const int hh = n >> 6, d = n & 63;
                const int b0 = r >> 11, s0 = r & 2047;
                const int b1 = (r + 8) >> 11, s1 = (r + 8) & 2047;
                uint32_t ph, pl;
                split2(v0, v1, ph, pl);
                size_t o0 = (((size_t)(b0 * HN + hh)) * SEQ + s0) * HD + d;
                *reinterpret_cast<uint32_t*>(Ch + o0) = ph;
                *reinterpret_cast<uint32_t*>(Cl + o0) = pl;
                split2(v2, v3, ph, pl);
                size_t o1 = (((size_t)(b1 * HN + hh)) * SEQ + s1) * HD + d;
                *reinterpret_cast<uint32_t*>(Ch + o1) = ph;
                *reinterpret_cast<uint32_t*>(Cl + o1) = pl;
            } else {  // MODE 3: V transposed [b,g,d,s]
                const int gg = n >> 6, d = n & 63;
                const int b0 = r >> 11, s0 = r & 2047;
                const int b1 = (r + 8) >> 11, s1 = (r + 8) & 2047;
                const size_t base0 = ((size_t)(b0 * NG + gg)) * HD;
                const size_t base1 = ((size_t)(b1 * NG + gg)) * HD;
                float vals[4] = {v0, v1, v2, v3};
                size_t offs[4] = {
                    (base0 + d) * SEQ + s0, (base0 + d + 1) * SEQ + s0,
                    (base1 + d) * SEQ + s1, (base1 + d + 1) * SEQ + s1 };
                #pragma unroll
                for (int j = 0; j < 4; j++) {
                    bf16 hb = __float2bfloat16(vals[j]);
                    bf16 lb = __float2bfloat16(vals[j] - __bfloat162float(hb));
                    Ch[offs[j]] = hb;
                    Cl[offs[j]] = lb;
                }
            }
        }
    }
}

// ---------------------------------------------------------------------------
// Flash attention, 3x-bf16 mma, pre-split operands, ldmatrix fragments,
// P kept in registers, cp.async double-buffered K/V tiles.
// Block = (b, h, 128-query tile), 256 threads (8 warps x 16 q-rows).
// smem/stage: Kh,Kl [64 key][72 d] + Vh,Vl [64 d][72 key] bf16 = 36864 B.
// ---------------------------------------------------------------------------
#define AKP 72
#define AK_BYTES (64 * AKP * 2)        // 9216
#define ASTAGE   (4 * AK_BYTES)        // 36864
#define ATTN_SMEM (2 * ASTAGE)         // 73728

__global__ __launch_bounds__(256, 2) void attn_kernel(
    const bf16* __restrict__ Qh, const bf16* __restrict__ Ql,
    const bf16* __restrict__ Kh, const bf16* __restrict__ Kl,
    const bf16* __restrict__ Vh, const bf16* __restrict__ Vl,
    bf16* __restrict__ Oh, bf16* __restrict__ Ol)
{
    extern __shared__ char smc[];
    const uint32_t sbase = (uint32_t)__cvta_generic_to_shared(smc);

    const int tid  = threadIdx.x;
    const int lane = tid & 31;
    const int wid  = tid >> 5;
    const int g = lane >> 2, c = lane & 3;
    const int quad = lane >> 3, r8 = lane & 7;
    const int wr0 = wid * 16;

    const int qt = blockIdx.x;
    const int h  = blockIdx.y;
    const int b  = blockIdx.z;
    const int gh = h >> 2;              // REP = 4

    const size_t koff = ((size_t)(b * NG + gh)) * SEQ * HD;   // [b,g,s,d]
    const size_t voff = ((size_t)(b * NG + gh)) * HD * SEQ;   // [b,g,d,s]

    // Q fragments in registers (bf16 hi/lo, direct 4B loads)
    const bf16* qbh = Qh + (((size_t)(b * NH + h)) * SEQ + qt * 128 + wr0) * HD;
    const bf16* qbl = Ql + (((size_t)(b * NH + h)) * SEQ + qt * 128 + wr0) * HD;
    uint32_t qh[4][4], ql[4][4];
    #pragma unroll
    for (int kt = 0; kt < 4; kt++) {
        const int o0 = g * HD + kt * 16 + 2 * c;
        qh[kt][0] = *(const uint32_t*)(qbh + o0);
        qh[kt][1] = *(const uint32_t*)(qbh + o0 + 8 * HD);
        qh[kt][2] = *(const uint32_t*)(qbh + o0 + 8);
        qh[kt][3] = *(const uint32_t*)(qbh + o0 + 8 * HD + 8);
        ql[kt][0] = *(const uint32_t*)(qbl + o0);
        ql[kt][1] = *(const uint32_t*)(qbl + o0 + 8 * HD);
        ql[kt][2] = *(const uint32_t*)(qbl + o0 + 8);
        ql[kt][3] = *(const uint32_t*)(qbl + o0 + 8 * HD + 8);
    }

    auto fill = [&](int t, int st) {
        const uint32_t s0 = sbase + st * ASTAGE;
        #pragma unroll
        for (int i = 0; i < 2; i++) {
            const int idx = tid + i * 256;           // 0..511
            const int r = idx >> 3, q = (idx & 7) * 8;
            const uint32_t so = (r * AKP + q) * 2;
            const size_t gk = koff + (size_t)(t * 64 + r) * HD + q;
            cp16(s0 + so,            Kh + gk);
            cp16(s0 + AK_BYTES + so, Kl + gk);
            const size_t gv = voff + (size_t)r * SEQ + t * 64 + q;
            cp16(s0 + 2 * AK_BYTES + so, Vh + gv);
            cp16(s0 + 3 * AK_BYTES + so, Vl + gv);
        }
    };

    float m0 = -1e30f, m1 = -1e30f, l0 = 0.0f, l1 = 0.0f;
    float oacc[8][4];
    #pragma unroll
    for (int nt = 0; nt < 8; nt++)
        #pragma unroll
        for (int j = 0; j < 4; j++) oacc[nt][j] = 0.0f;

    const int lrow = (quad >> 1) * 8 + r8;   // B-frag lane row
    const int lcol = (quad & 1) * 8;         // B-frag lane col

    fill(0, 0); CP_COMMIT();

    for (int t = 0; t < SEQ / 64; t++) {
        CP_WAIT0();
        __syncthreads();
        if (t + 1 < SEQ / 64) { fill(t + 1, (t + 1) & 1); CP_COMMIT(); }
        const uint32_t sK = sbase + (t & 1) * ASTAGE;
        const uint32_t sV = sK + 2 * AK_BYTES;

        // ---- S = Q @ K^T ----
        float sv[8][4];
        #pragma unroll
        for (int nt = 0; nt < 8; nt++)
            #pragma unroll
            for (int j = 0; j < 4; j++) sv[nt][j] = 0.0f;

        #pragma unroll
        for (int np = 0; np < 4; np++) {
            #pragma unroll
            for (int kt = 0; kt < 4; kt++) {
                const uint32_t ka = sK + ((np * 16 + lrow) * AKP + kt * 16 + lcol) * 2;
                uint32_t h0, h1, h2, h3, lo0, lo1, lo2, lo3;
                ldsm4(h0, h1, h2, h3, ka);
                ldsm4(lo0, lo1, lo2, lo3, ka + AK_BYTES);
                mma_bf16(sv[2*np],   ql[kt], h0, h1);
                mma_bf16(sv[2*np],   qh[kt], lo0, lo1);
                mma_bf16(sv[2*np],   qh[kt], h0, h1);
                mma_bf16(sv[2*np+1], ql[kt], h2, h3);
                mma_bf16(sv[2*np+1], qh[kt], lo2, lo3);
                mma_bf16(sv[2*np+1], qh[kt], h2, h3);
            }
        }

        // ---- online softmax (scale pre-folded into K) ----
        float mx0 = -1e30f, mx1 = -1e30f;
        #pragma unroll
        for (int nt = 0; nt < 8; nt++) {
            mx0 = fmaxf(mx0, fmaxf(sv[nt][0], sv[nt][1]));
            mx1 = fmaxf(mx1, fmaxf(sv[nt][2], sv[nt][3]));
        }
        mx0 = fmaxf(mx0, __shfl_xor_sync(0xffffffffu, mx0, 1));
        mx0 = fmaxf(mx0, __shfl_xor_sync(0xffffffffu, mx0, 2));
        mx1 = fmaxf(mx1, __shfl_xor_sync(0xffffffffu, mx1, 1));
        mx1 = fmaxf(mx1, __shfl_xor_sync(0xffffffffu, mx1, 2));

        const float nm0 = fmaxf(m0, mx0), nm1 = fmaxf(m1, mx1);
        const float corr0 = __expf(m0 - nm0), corr1 = __expf(m1 - nm1);
        float ls0 = 0.0f, ls1 = 0.0f;
        #pragma unroll
        for (int nt = 0; nt < 8; nt++) {
            sv[nt][0] = __expf(sv[nt][0] - nm0);
            sv[nt][1] = __expf(sv[nt][1] - nm0);
            sv[nt][2] = __expf(sv[nt][2] - nm1);
            sv[nt][3] = __expf(sv[nt][3] - nm1);
            ls0 += sv[nt][0] + sv[nt][1];
            ls1 += sv[nt][2] + sv[nt][3];
        }
        ls0 += __shfl_xor_sync(0xffffffffu, ls0, 1);
        ls0 += __shfl_xor_sync(0xffffffffu, ls0, 2);
        ls1 += __shfl_xor_sync(0xffffffffu, ls1, 1);
        ls1 += __shfl_xor_sync(0xffffffffu, ls1, 2);
        l0 = l0 * corr0 + ls0; m0 = nm0;
        l1 = l1 * corr1 + ls1; m1 = nm1;
        #pragma unroll
        for (int nt = 0; nt < 8; nt++) {
            oacc[nt][0] *= corr0; oacc[nt][1] *= corr0;
            oacc[nt][2] *= corr1; oacc[nt][3] *= corr1;
        }

        // ---- O += P @ V ; P lives in registers (sv holds exp values) ----
        #pragma unroll
        for (int kt = 0; kt < 4; kt++) {
            uint32_t ph[4], pl[4];
            split2(sv[2*kt][0],   sv[2*kt][1],   ph[0], pl[0]);
            split2(sv[2*kt][2],   sv[2*kt][3],   ph[1], pl[1]);
            split2(sv[2*kt+1][0], sv[2*kt+1][1], ph[2], pl[2]);
            split2(sv[2*kt+1][2], sv[2*kt+1][3], ph[3], pl[3]);
            #pragma unroll
            for (int np = 0; np < 4; np++) {
                const uint32_t va = sV + ((np * 16 + lrow) * AKP + kt * 16 + lcol) * 2;
                uint32_t h0, h1, h2, h3, lo0, lo1, lo2, lo3;
                ldsm4(h0, h1, h2, h3, va);
                ldsm4(lo0, lo1, lo2, lo3, va + AK_BYTES);
                mma_bf16(oacc[2*np],   pl, h0, h1);
                mma_bf16(oacc[2*np],   ph, lo0, lo1);
                mma_bf16(oacc[2*np],   ph, h0, h1);
                mma_bf16(oacc[2*np+1], pl, h2, h3);
                mma_bf16(oacc[2*np+1], ph, lo2, lo3);
                mma_bf16(oacc[2*np+1], ph, h2, h3);
            }
        }
    }

    // ---- epilogue: normalize, split, store bf16 hi/lo to [b,s,h*64+d] ----
    const float inv0 = 1.0f / l0, inv1 = 1.0f / l1;
    const int s0 = qt * 128 + wr0 + g;
    const size_t ob0 = ((size_t)b * SEQ + s0) * HID + h * HD;
    const size_t ob1 = ((size_t)b * SEQ + s0 + 8) * HID + h * HD;
    #pragma unroll
    for (int nt = 0; nt < 8; nt++) {
        const int d = nt * 8 + 2 * c;
        uint32_t ph, pl;
        split2(oacc[nt][0] * inv0, oacc[nt][1] * inv0, ph, pl);
        *reinterpret_cast<uint32_t*>(Oh + ob0 + d) = ph;
        *reinterpret_cast<uint32_t*>(Ol + ob0 + d) = pl;
        split2(oacc[nt][2] * inv1, oacc[nt][3] * inv1, ph, pl);
        *reinterpret_cast<uint32_t*>(Oh + ob1 + d) = ph;
        *reinterpret_cast<uint32_t*>(Ol + ob1 + d) = pl;
    }
}

// ---------------------------------------------------------------------------
extern "C" void kernel_launch(void* const* d_in, const int* in_sizes, int n_in,
                              void* d_out, int out_size)
{
    const float* X  = (const float*)d_in[0];
    const float* Wq = (const float*)d_in[1];
    const float* bq = (const float*)d_in[2];
    const float* Wk = (const float*)d_in[3];
    const float* bk = (const float*)d_in[4];
    const float* Wv = (const float*)d_in[5];
    const float* bv = (const float*)d_in[6];
    const float* Wo = (const float*)d_in[7];
    const float* bo = (const float*)d_in[8];
    float* out = (float*)d_out;

    bf16 *xh, *xl, *wqh, *wql, *wkh, *wkl, *wvh, *wvl, *woh, *wol;
    bf16 *qh, *ql, *kh, *kl, *vh, *vl, *oh, *ol;
    cudaGetSymbolAddress((void**)&xh,  g_xh);  cudaGetSymbolAddress((void**)&xl,  g_xl);
    cudaGetSymbolAddress((void**)&wqh, g_wqh); cudaGetSymbolAddress((void**)&wql, g_wql);
    cudaGetSymbolAddress((void**)&wkh, g_wkh); cudaGetSymbolAddress((void**)&wkl, g_wkl);
    cudaGetSymbolAddress((void**)&wvh, g_wvh); cudaGetSymbolAddress((void**)&wvl, g_wvl);
    cudaGetSymbolAddress((void**)&woh, g_woh); cudaGetSymbolAddress((void**)&wol, g_wol);
    cudaGetSymbolAddress((void**)&qh,  g_qh);  cudaGetSymbolAddress((void**)&ql,  g_ql);
    cudaGetSymbolAddress((void**)&kh,  g_kh);  cudaGetSymbolAddress((void**)&kl,  g_kl);
    cudaGetSymbolAddress((void**)&vh,  g_vh);  cudaGetSymbolAddress((void**)&vl,  g_vl);
    cudaGetSymbolAddress((void**)&oh,  g_oh);  cudaGetSymbolAddress((void**)&ol,  g_ol);

    cudaFuncSetAttribute(gemm_kernel<0>, cudaFuncAttributeMaxDynamicSharedMemorySize, GEMM_SMEM);
    cudaFuncSetAttribute(gemm_kernel<1>, cudaFuncAttributeMaxDynamicSharedMemorySize, GEMM_SMEM);
    cudaFuncSetAttribute(gemm_kernel<2>, cudaFuncAttributeMaxDynamicSharedMemorySize, GEMM_SMEM);
    cudaFuncSetAttribute(gemm_kernel<3>, cudaFuncAttributeMaxDynamicSharedMemorySize, GEMM_SMEM);
    cudaFuncSetAttribute(attn_kernel, cudaFuncAttributeMaxDynamicSharedMemorySize, ATTN_SMEM);

    // ---- convert fp32 -> bf16 hi/lo ----
    auto conv = [&](const float* s, bf16* h, bf16* l, int n) {
        const int n4 = n / 4;
        convert_kernel<<<(n4 + 255) / 256, 256>>>(s, h, l, n4);
    };
    conv(X,  xh,  xl,  MTOT * HID);
    conv(Wq, wqh, wql, HID * HID);
    conv(Wk, wkh, wkl, HID * KVD);
    conv(Wv, wvh, wvl, HID * KVD);
    conv(Wo, woh, wol, HID * HID);

    dim3 blk(256);
    // Q projection -> bf16 [b,h,s,d]
    gemm_kernel<1><<<dim3(HID / 128, MTOT / 128), blk, GEMM_SMEM>>>(
        xh, xl, wqh, wql, bq, nullptr, qh, ql, MTOT, HID, HID);
    // K projection (scaled by 1/8) -> bf16 [b,g,s,d]
    gemm_kernel<2><<<dim3(KVD / 128, MTOT / 128), blk, GEMM_SMEM>>>(
        xh, xl, wkh, wkl, bk, nullptr, kh, kl, MTOT, KVD, HID);
    // V projection -> bf16 transposed [b,g,d,s]
    gemm_kernel<3><<<dim3(KVD / 128, MTOT / 128), blk, GEMM_SMEM>>>(
        xh, xl, wvh, wvl, bv, nullptr, vh, vl, MTOT, KVD, HID);
    // Attention -> bf16 hi/lo [b,s,h*d]
    attn_kernel<<<dim3(SEQ / 128, NH, BATCH), blk, ATTN_SMEM>>>(
        qh, ql, kh, kl, vh, vl, oh, ol);
    // Output projection -> fp32 d_out
    gemm_kernel<0><<<dim3(HID / 128, MTOT / 128), blk, GEMM_SMEM>>>(
        oh, ol, woh, wol, bo, out, nullptr, nullptr, MTOT, HID, HID);
}